// round 1
// baseline (speedup 1.0000x reference)
#include <cuda_runtime.h>

// Problem constants (fixed by reference_code)
#define Bc 2
#define Nc 65536
#define Hc 128
#define Wc 128
#define HWc 16384
#define Gsplit 32              // split-K factor over gaussians
#define KN (Nc / Gsplit)       // 2048 gaussians per block
#define KC 32                  // chunk of gaussians staged in smem
#define NTILES 8               // 2 x-tiles (64 wide) * 4 y-tiles (32 tall)
#define TDIMX 64
#define TDIMY 32

// Scratch (static __device__ arrays — no allocation at runtime)
__device__ float4 g_params[Bc * Nc];                  // proj_x, proj_y, a=-0.5/var, opacity
__device__ float  g_part[Bc * Gsplit * 4 * HWc];      // split-K partials (r,g,b,den)

// ---------------------------------------------------------------------------
// Kernel 1: per-(camera, gaussian) projection parameters
// ---------------------------------------------------------------------------
__global__ void k_params(const float* __restrict__ pos,
                         const float* __restrict__ opa,
                         const float* __restrict__ scl,
                         const float* __restrict__ qv,
                         const float* __restrict__ tv,
                         const float* __restrict__ fx_,
                         const float* __restrict__ fy_,
                         const float* __restrict__ cx_,
                         const float* __restrict__ cy_) {
    int idx = blockIdx.x * blockDim.x + threadIdx.x;
    if (idx >= Bc * Nc) return;
    int b = idx >> 16;            // Nc = 65536
    int n = idx & (Nc - 1);

    float qw = qv[b * 4 + 0], qx = qv[b * 4 + 1], qy = qv[b * 4 + 2], qz = qv[b * 4 + 3];
    float inv = rsqrtf(qw * qw + qx * qx + qy * qy + qz * qz);
    qw *= inv; qx *= inv; qy *= inv; qz *= inv;

    float R00 = 1.f - 2.f * (qy * qy + qz * qz);
    float R01 = 2.f * (qx * qy - qz * qw);
    float R02 = 2.f * (qx * qz + qy * qw);
    float R10 = 2.f * (qx * qy + qz * qw);
    float R11 = 1.f - 2.f * (qx * qx + qz * qz);
    float R12 = 2.f * (qy * qz - qx * qw);
    float R20 = 2.f * (qx * qz - qy * qw);
    float R21 = 2.f * (qy * qz + qx * qw);
    float R22 = 1.f - 2.f * (qx * qx + qy * qy);

    float px = pos[3 * n], py = pos[3 * n + 1], pz = pos[3 * n + 2];
    // p_cam = positions @ R.T + t  -> p_cam[i] = sum_j pos[j] * R[i][j]
    float cxm = R00 * px + R01 * py + R02 * pz + tv[b * 3 + 0];
    float cym = R10 * px + R11 * py + R12 * pz + tv[b * 3 + 1];
    float czm = R20 * px + R21 * py + R22 * pz + tv[b * 3 + 2];

    float projx = cxm / czm * fx_[0] + cx_[0];
    float projy = cym / czm * fy_[0] + cy_[0];
    float s = scl[n];
    float a = -0.5f / (s * s);

    g_params[idx] = make_float4(projx, projy, a, opa[n]);
}

// ---------------------------------------------------------------------------
// Kernel 2: fused separable splat / rank-1 GEMM with split-K
//   block = 256 threads, tile = 64x * 32y pixels, 2048 gaussians
//   per chunk of 32 gaussians: stage u[k][64], v[k][32], colors[k] in smem
// ---------------------------------------------------------------------------
__global__ void __launch_bounds__(256) k_splat(const float* __restrict__ colors) {
    __shared__ float  us[KC][TDIMX];   // u[k][x]  (8 KB)
    __shared__ float  vs[KC][TDIMY];   // v[k][y]  (4 KB) — opacity folded in
    __shared__ float4 cs[KC];          // colors   (512 B)

    const int t    = threadIdx.x;
    const int g    = blockIdx.x;          // k-split index
    const int tile = blockIdx.y;          // 0..7
    const int b    = blockIdx.z;          // camera
    const int x0   = (tile & 1) * TDIMX;
    const int y0   = (tile >> 1) * TDIMY;
    const int kbase0 = g * KN;

    // thread -> 4x * 2y pixel micro-tile
    const int tx  = t & 15;               // px base = x0 + 4*tx
    const int tyy = t >> 4;               // py base = y0 + 2*tyy
    const int xu  = t & 63, ku0 = t >> 6; // u-stage mapping
    const int yv  = t & 31, kv0 = t >> 5; // v-stage mapping

    float acc[2][4][4];
#pragma unroll
    for (int yi = 0; yi < 2; yi++)
#pragma unroll
        for (int xi = 0; xi < 4; xi++)
#pragma unroll
            for (int ch = 0; ch < 4; ch++) acc[yi][xi][ch] = 0.f;

    const float4* __restrict__ prm = &g_params[b * Nc];

    for (int kb = 0; kb < KN; kb += KC) {
        const int kbase = kbase0 + kb;
        __syncthreads();   // previous chunk consumers done

        // ---- stage u: 32k x 64x, conflict-free STS (consecutive x per warp)
#pragma unroll
        for (int i = 0; i < 8; i++) {
            int k = ku0 + i * 4;
            float4 pr = prm[kbase + k];
            float dx = (float)(x0 + xu) - pr.x;
            us[k][xu] = __expf(pr.z * dx * dx);
        }
        // ---- stage v: 32k x 32y (opacity folded in)
#pragma unroll
        for (int i = 0; i < 4; i++) {
            int k = kv0 + i * 8;
            float4 pr = prm[kbase + k];
            float dy = (float)(y0 + yv) - pr.y;
            vs[k][yv] = pr.w * __expf(pr.z * dy * dy);
        }
        // ---- stage colors
        if (t < KC) {
            int n = kbase + t;
            cs[t] = make_float4(colors[3 * n], colors[3 * n + 1], colors[3 * n + 2], 0.f);
        }
        __syncthreads();

        // ---- inner rank-1 accumulation: 40 FMA + 4 LDS per k per thread
#pragma unroll 8
        for (int k = 0; k < KC; k++) {
            float4 u4 = *reinterpret_cast<const float4*>(&us[k][tx * 4]);
            float2 v2 = *reinterpret_cast<const float2*>(&vs[k][tyy * 2]);
            float4 c  = cs[k];
            float uu[4] = {u4.x, u4.y, u4.z, u4.w};
            float vv[2] = {v2.x, v2.y};
#pragma unroll
            for (int yi = 0; yi < 2; yi++) {
#pragma unroll
                for (int xi = 0; xi < 4; xi++) {
                    float w = vv[yi] * uu[xi];
                    acc[yi][xi][0] += w * c.x;
                    acc[yi][xi][1] += w * c.y;
                    acc[yi][xi][2] += w * c.z;
                    acc[yi][xi][3] += w;
                }
            }
        }
    }

    // ---- write deterministic split-K partials
    const int base_bg = ((b * Gsplit + g) * 4) * HWc;
#pragma unroll
    for (int yi = 0; yi < 2; yi++) {
        int pyy = y0 + tyy * 2 + yi;
#pragma unroll
        for (int xi = 0; xi < 4; xi++) {
            int pxx  = x0 + tx * 4 + xi;
            int pidx = pyy * Wc + pxx;
#pragma unroll
            for (int ch = 0; ch < 4; ch++)
                g_part[base_bg + ch * HWc + pidx] = acc[yi][xi][ch];
        }
    }
}

// ---------------------------------------------------------------------------
// Kernel 3: reduce split-K partials, add 32*EPS (one EPS per reference chunk),
//           divide, write (B,3,H,W)
// ---------------------------------------------------------------------------
__global__ void k_finalize(float* __restrict__ out) {
    int idx = blockIdx.x * blockDim.x + threadIdx.x;
    if (idx >= Bc * HWc) return;
    int b = idx >> 14;           // HWc = 16384
    int p = idx & (HWc - 1);

    float r = 0.f, gg = 0.f, bb = 0.f;
    float d = 32.0f * 1e-8f;     // n_chunks(=32) * EPS added by reference scan
#pragma unroll
    for (int s = 0; s < Gsplit; s++) {
        int base = ((b * Gsplit + s) * 4) * HWc + p;
        r  += g_part[base];
        gg += g_part[base + HWc];
        bb += g_part[base + 2 * HWc];
        d  += g_part[base + 3 * HWc];
    }
    float inv = 1.0f / fmaxf(d, 1e-8f);
    out[(b * 3 + 0) * HWc + p] = r  * inv;
    out[(b * 3 + 1) * HWc + p] = gg * inv;
    out[(b * 3 + 2) * HWc + p] = bb * inv;
}

// ---------------------------------------------------------------------------
extern "C" void kernel_launch(void* const* d_in, const int* in_sizes, int n_in,
                              void* d_out, int out_size) {
    const float* pos = (const float*)d_in[0];
    const float* col = (const float*)d_in[1];
    const float* opa = (const float*)d_in[2];
    const float* scl = (const float*)d_in[3];
    const float* qv  = (const float*)d_in[4];
    const float* tv  = (const float*)d_in[5];
    const float* fx  = (const float*)d_in[6];
    const float* fy  = (const float*)d_in[7];
    const float* cx  = (const float*)d_in[8];
    const float* cy  = (const float*)d_in[9];

    k_params<<<(Bc * Nc) / 256, 256>>>(pos, opa, scl, qv, tv, fx, fy, cx, cy);

    dim3 grid(Gsplit, NTILES, Bc);   // 32 * 8 * 2 = 512 blocks
    k_splat<<<grid, 256>>>(col);

    k_finalize<<<(Bc * HWc) / 256, 256>>>((float*)d_out);
}